// round 13
// baseline (speedup 1.0000x reference)
#include <cuda_runtime.h>
#include <cuda_bf16.h>
#include <cuda_fp16.h>
#include <cstdint>
#define B_ 2
#define S_ 2048
#define D_ 1024
#define H_ 16
#define NACT (B_*S_*D_)

__device__ float g_V[NACT];                                   // fp32 V projection
__device__ __nv_bfloat16 g_Ah[3*NACT], g_Al[3*NACT];          // act hi/lo (slot0 reused for ctx)
__device__ __nv_bfloat16 g_Bh[4*D_*D_], g_Bl[4*D_*D_];        // wgt hi/lo (Wq,Wk,Wv,Wo)
__device__ __nv_bfloat16 g_Qh[NACT], g_Ql[NACT];              // attn Q planes (scaled)
__device__ __nv_bfloat16 g_Kh[NACT], g_Kl[NACT];              // attn K planes
__device__ __half g_Vt[NACT];                                 // V^T fp16 [b][h][d][s]
__device__ uint32_t g_mb[S_*S_/32];                           // mask bitplane

__device__ __forceinline__ uint32_t smem_u32(const void* p){
    uint32_t a; asm("{ .reg .u64 t; cvta.to.shared.u64 t, %1; cvt.u32.u64 %0, t; }":"=r"(a):"l"(p)); return a;
}
// volatile: must not hoist above __syncthreads
__device__ __forceinline__ void ldsm4(uint32_t* r, uint32_t a){
    asm volatile("ldmatrix.sync.aligned.m8n8.x4.shared.b16 {%0,%1,%2,%3}, [%4];"
        :"=r"(r[0]),"=r"(r[1]),"=r"(r[2]),"=r"(r[3]):"r"(a));
}
// NON-volatile: pure register ops — let the compiler interleave independent MMAs
__device__ __forceinline__ void mmabf(float* c, const uint32_t* a, uint32_t b0, uint32_t b1){
    asm("mma.sync.aligned.m16n8k16.row.col.f32.bf16.bf16.f32 "
        "{%0,%1,%2,%3}, {%4,%5,%6,%7}, {%8,%9}, {%0,%1,%2,%3};"
        :"+f"(c[0]),"+f"(c[1]),"+f"(c[2]),"+f"(c[3])
        :"r"(a[0]),"r"(a[1]),"r"(a[2]),"r"(a[3]),"r"(b0),"r"(b1));
}
__device__ __forceinline__ void mmaf16(float* c, const uint32_t* a, uint32_t b0, uint32_t b1){
    asm("mma.sync.aligned.m16n8k16.row.col.f32.f16.f16.f32 "
        "{%0,%1,%2,%3}, {%4,%5,%6,%7}, {%8,%9}, {%0,%1,%2,%3};"
        :"+f"(c[0]),"+f"(c[1]),"+f"(c[2]),"+f"(c[3])
        :"r"(a[0]),"r"(a[1]),"r"(a[2]),"r"(a[3]),"r"(b0),"r"(b1));
}
__device__ __forceinline__ void cpa16(uint32_t d, const void* s){
    asm volatile("cp.async.cg.shared.global [%0], [%1], 16;"::"r"(d),"l"(s):"memory");
}
__device__ __forceinline__ uint32_t pk2(float a, float b){
    __nv_bfloat162 h = __floats2bfloat162_rn(a, b);
    return *reinterpret_cast<uint32_t*>(&h);
}
__device__ __forceinline__ uint32_t pkh2(float a, float b){
    __half2 h = __floats2half2_rn(a, b);
    return *reinterpret_cast<uint32_t*>(&h);
}
__device__ __forceinline__ float bflo(float v){
    return v - __bfloat162float(__float2bfloat16(v));
}
__device__ __forceinline__ float ex2(float x){
    float r; asm("ex2.approx.ftz.f32 %0, %1;":"=f"(r):"f"(x)); return r;
}

// ---------------- mask -> bitplane ----------------
__global__ void __launch_bounds__(256)
maskbits_kernel(const int* __restrict__ mask, uint32_t* __restrict__ bits)
{
    int i = blockIdx.x * 256 + threadIdx.x;
    uint32_t b = __ballot_sync(0xffffffffu, mask[i] != 0);
    if ((threadIdx.x & 31) == 0) bits[i >> 5] = b;
}

// ---------------- z-batched fp32 -> bf16 hi/lo ----------------
__global__ void __launch_bounds__(256)
cvt3_kernel(const float* __restrict__ i0, const float* __restrict__ i1,
            const float* __restrict__ i2, __nv_bfloat16* __restrict__ hi,
            __nv_bfloat16* __restrict__ lo, int slot_u2)
{
    int z = blockIdx.y;
    const float* in = (z == 0) ? i0 : (z == 1) ? i1 : i2;
    int i = blockIdx.x * 256 + threadIdx.x;
    float4 v = ((const float4*)in)[i];
    float a[4] = {v.x, v.y, v.z, v.w};
    unsigned short h[4], l[4];
    #pragma unroll
    for (int j = 0; j < 4; j++) {
        __nv_bfloat16 hb = __float2bfloat16(a[j]);
        h[j] = __bfloat16_as_ushort(hb);
        l[j] = __bfloat16_as_ushort(__float2bfloat16(a[j] - __bfloat162float(hb)));
    }
    size_t o = (size_t)z * slot_u2 + i;
    ((uint2*)hi)[o] = make_uint2(h[0]|((uint32_t)h[1]<<16), h[2]|((uint32_t)h[3]<<16));
    ((uint2*)lo)[o] = make_uint2(l[0]|((uint32_t)l[1]<<16), l[2]|((uint32_t)l[3]<<16));
}
__global__ void __launch_bounds__(256)
cvt4_kernel(const float* __restrict__ i0, const float* __restrict__ i1,
            const float* __restrict__ i2, const float* __restrict__ i3,
            __nv_bfloat16* __restrict__ hi, __nv_bfloat16* __restrict__ lo, int slot_u2)
{
    int z = blockIdx.y;
    const float* in = (z == 0) ? i0 : (z == 1) ? i1 : (z == 2) ? i2 : i3;
    int i = blockIdx.x * 256 + threadIdx.x;
    float4 v = ((const float4*)in)[i];
    float a[4] = {v.x, v.y, v.z, v.w};
    unsigned short h[4], l[4];
    #pragma unroll
    for (int j = 0; j < 4; j++) {
        __nv_bfloat16 hb = __float2bfloat16(a[j]);
        h[j] = __bfloat16_as_ushort(hb);
        l[j] = __bfloat16_as_ushort(__float2bfloat16(a[j] - __bfloat162float(hb)));
    }
    size_t o = (size_t)z * slot_u2 + i;
    ((uint2*)hi)[o] = make_uint2(h[0]|((uint32_t)h[1]<<16), h[2]|((uint32_t)h[3]<<16));
    ((uint2*)lo)[o] = make_uint2(l[0]|((uint32_t)l[1]<<16), l[2]|((uint32_t)l[3]<<16));
}
// V[b][s][h*64+d] -> Vt[b][h][d][s] fp16
__global__ void __launch_bounds__(256)
cvtT_kernel(const float* __restrict__ V, __half* __restrict__ oh)
{
    __shared__ float tile[32][33];
    const int s0 = blockIdx.x*32, d0 = blockIdx.y*32, b = blockIdx.z;
    const int tx = threadIdx.x & 31, ty = threadIdx.x >> 5;
    #pragma unroll
    for (int i = 0; i < 4; i++)
        tile[ty+8*i][tx] = V[((size_t)(b*S_+s0+ty+8*i))*D_ + d0+tx];
    __syncthreads();
    const int hh = d0 >> 6, dl = d0 & 63;
    #pragma unroll
    for (int i = 0; i < 4; i++) {
        int dr = ty + 8*i;
        size_t a = ((size_t)((b*H_+hh)*64 + dl + dr))*S_ + s0 + tx;
        oh[a] = __float2half(tile[tx][dr]);
    }
}

// ---------------------------------------------------------------------------
// HMMA bf16x3-split GEMM core. MMAs issued TERM-MAJOR within each ldsm block:
// 4 independent accumulators per term before any acc is revisited.
// ---------------------------------------------------------------------------
static constexpr int PLN = 128 * 80;
static constexpr int STG = 4 * PLN;
static constexpr int GSM = 2 * STG;

#define GEMM_CORE(gAh, gAl, gBh, gBl, acc) do { \
    const int crow = t >> 1, coff = (t & 1) * 32; \
    const char* pAh = (const char*)((gAh) + (size_t)(bm + crow) * D_) + coff; \
    const char* pAl = (const char*)((gAl) + (size_t)(bm + crow) * D_) + coff; \
    const char* pBh = (const char*)((gBh) + (size_t)(bn + crow) * D_) + coff; \
    const char* pBl = (const char*)((gBl) + (size_t)(bn + crow) * D_) + coff; \
    const uint32_t dst0 = sb + crow * 80 + coff; \
    const int NCH = D_ / 32; \
    for (int c = 0; c < NCH; c++) { \
        const int s = c & 1; \
        if (c == 0) { \
            uint32_t d = dst0; int go = 0; \
            cpa16(d, pAh+go); cpa16(d+16, pAh+go+16); \
            cpa16(d+PLN, pAl+go); cpa16(d+PLN+16, pAl+go+16); \
            cpa16(d+2*PLN, pBh+go); cpa16(d+2*PLN+16, pBh+go+16); \
            cpa16(d+3*PLN, pBl+go); cpa16(d+3*PLN+16, pBl+go+16); \
            asm volatile("cp.async.commit_group;" ::: "memory"); \
        } \
        if (c + 1 < NCH) { \
            uint32_t d = dst0 + (s^1) * STG; int go = (c+1) * 64; \
            cpa16(d, pAh+go); cpa16(d+16, pAh+go+16); \
            cpa16(d+PLN, pAl+go); cpa16(d+PLN+16, pAl+go+16); \
            cpa16(d+2*PLN, pBh+go); cpa16(d+2*PLN+16, pBh+go+16); \
            cpa16(d+3*PLN, pBl+go); cpa16(d+3*PLN+16, pBl+go+16); \
            asm volatile("cp.async.commit_group;" ::: "memory"); \
            asm volatile("cp.async.wait_group 1;" ::: "memory"); \
        } else { \
            asm volatile("cp.async.wait_group 0;" ::: "memory"); \
        } \
        __syncthreads(); \
        const uint32_t base = sb + s * STG; \
        const int arow = mw + (lane & 15); \
        const int brow = nw + (lane & 7) + ((lane >> 4) << 3); \
        _Pragma("unroll") \
        for (int ks = 0; ks < 2; ks++) { \
            const int acol = ks * 32 + ((lane >> 4) << 4); \
            const int bcol = ks * 32 + (((lane >> 3) & 1) << 4); \
            uint32_t ah[2][4], al[2][4]; \
            _Pragma("unroll") \
            for (int mi = 0; mi < 2; mi++) { \
                uint32_t ad = base + (arow + mi * 16) * 80 + acol; \
                ldsm4(ah[mi], ad); ldsm4(al[mi], ad + PLN); \
            } \
            _Pragma("unroll") \
            for (int nf = 0; nf < 4; nf++) { \
                uint32_t bd = base + 2 * PLN + (brow + nf * 16) * 80 + bcol; \
                uint32_t bh[4], bl[4]; \
                ldsm4(bh, bd); ldsm4(bl, bd + PLN); \
                /* term hh: 4 independent accs */ \
                mmabf(acc[0][2*nf],   ah[0], bh[0], bh[1]); \
                mmabf(acc[0][2*nf+1], ah[0], bh[2], bh[3]); \
                mmabf(acc[1][2*nf],   ah[1], bh[0], bh[1]); \
                mmabf(acc[1][2*nf+1], ah[1], bh[2], bh[3]); \
                /* term hl */ \
                mmabf(acc[0][2*nf],   ah[0], bl[0], bl[1]); \
                mmabf(acc[0][2*nf+1], ah[0], bl[2], bl[3]); \
                mmabf(acc[1][2*nf],   ah[1], bl[0], bl[1]); \
                mmabf(acc[1][2*nf+1], ah[1], bl[2], bl[3]); \
                /* term lh */ \
                mmabf(acc[0][2*nf],   al[0], bh[0], bh[1]); \
                mmabf(acc[0][2*nf+1], al[0], bh[2], bh[3]); \
                mmabf(acc[1][2*nf],   al[1], bh[0], bh[1]); \
                mmabf(acc[1][2*nf+1], al[1], bh[2], bh[3]); \
            } \
        } \
        __syncthreads(); \
    } \
} while (0)

// z-batched QKV projection: z=0 -> Q planes (scaled), z=1 -> K planes, z=2 -> V fp32
__global__ void __launch_bounds__(256, 2)
gemm_qkv(const __nv_bfloat16* __restrict__ Ah3, const __nv_bfloat16* __restrict__ Al3,
         const __nv_bfloat16* __restrict__ Bh4, const __nv_bfloat16* __restrict__ Bl4,
         const float* __restrict__ bq, const float* __restrict__ bk,
         const float* __restrict__ bv, float* __restrict__ Vout,
         __nv_bfloat16* __restrict__ Qh, __nv_bfloat16* __restrict__ Ql,
         __nv_bfloat16* __restrict__ Kh, __nv_bfloat16* __restrict__ Kl, float qsc)
{
    extern __shared__ __align__(128) char sm[];
    const uint32_t sb = smem_u32(sm);
    const int t = threadIdx.x, lane = t & 31, w = t >> 5;
    const int bm = blockIdx.y * 128, bn = blockIdx.x * 128;
    const int mw = (w >> 1) * 32, nw = (w & 1) * 64;
    const int z = blockIdx.z;
    const __nv_bfloat16* Ah = Ah3 + (size_t)z * NACT;
    const __nv_bfloat16* Al = Al3 + (size_t)z * NACT;
    const __nv_bfloat16* Bh = Bh4 + (size_t)z * D_ * D_;
    const __nv_bfloat16* Bl = Bl4 + (size_t)z * D_ * D_;
    const float* bias = (z == 0) ? bq : (z == 1) ? bk : bv;

    float acc[2][8][4] = {};
    GEMM_CORE(Ah, Al, Bh, Bl, acc);

    const float osc = (z == 0) ? qsc : 1.0f;
    #pragma unroll
    for (int mi = 0; mi < 2; mi++) {
        const int r0 = bm + mw + mi * 16 + (lane >> 2);
        #pragma unroll
        for (int nj = 0; nj < 8; nj++) {
            const int col = bn + nw + nj * 8 + (lane & 3) * 2;
            float2 bv2 = *(const float2*)&bias[col];
            float* c = acc[mi][nj];
            if (z == 2) {
                *(float2*)&Vout[(size_t)r0 * D_ + col] = make_float2(c[0] + bv2.x, c[1] + bv2.y);
                *(float2*)&Vout[(size_t)(r0 + 8) * D_ + col] = make_float2(c[2] + bv2.x, c[3] + bv2.y);
            } else {
                __nv_bfloat16* oh = (z == 0) ? Qh : Kh;
                __nv_bfloat16* ol = (z == 0) ? Ql : Kl;
                float v0 = (c[0] + bv2.x) * osc, v1 = (c[1] + bv2.y) * osc;
                float v2 = (c[2] + bv2.x) * osc, v3 = (c[3] + bv2.y) * osc;
                *(uint32_t*)&oh[(size_t)r0 * D_ + col]       = pk2(v0, v1);
                *(uint32_t*)&ol[(size_t)r0 * D_ + col]       = pk2(bflo(v0), bflo(v1));
                *(uint32_t*)&oh[(size_t)(r0 + 8) * D_ + col] = pk2(v2, v3);
                *(uint32_t*)&ol[(size_t)(r0 + 8) * D_ + col] = pk2(bflo(v2), bflo(v3));
            }
        }
    }
}

// O projection: fp32 out
__global__ void __launch_bounds__(256, 2)
gemm_o(const __nv_bfloat16* __restrict__ Ah, const __nv_bfloat16* __restrict__ Al,
       const __nv_bfloat16* __restrict__ Bh, const __nv_bfloat16* __restrict__ Bl,
       const float* __restrict__ bias, float* __restrict__ outf)
{
    extern __shared__ __align__(128) char sm[];
    const uint32_t sb = smem_u32(sm);
    const int t = threadIdx.x, lane = t & 31, w = t >> 5;
    const int bm = blockIdx.y * 128, bn = blockIdx.x * 128;
    const int mw = (w >> 1) * 32, nw = (w & 1) * 64;

    float acc[2][8][4] = {};
    GEMM_CORE(Ah, Al, Bh, Bl, acc);

    #pragma unroll
    for (int mi = 0; mi < 2; mi++) {
        const int r0 = bm + mw + mi * 16 + (lane >> 2);
        #pragma unroll
        for (int nj = 0; nj < 8; nj++) {
            const int col = bn + nw + nj * 8 + (lane & 3) * 2;
            float2 bv2 = *(const float2*)&bias[col];
            float* c = acc[mi][nj];
            *(float2*)&outf[(size_t)r0 * D_ + col] = make_float2(c[0] + bv2.x, c[1] + bv2.y);
            *(float2*)&outf[(size_t)(r0 + 8) * D_ + col] = make_float2(c[2] + bv2.x, c[3] + bv2.y);
        }
    }
}

// ---------------------------------------------------------------------------
// HMMA flash attention: QK^T bf16x3 (term-major MMA order), PV fp16x1,
// exp2 softmax, bitmask masking, bf16 hi/lo plane output.
// ---------------------------------------------------------------------------
static constexpr int KST  = 144;
static constexpr int KPL  = 64 * KST;      // 9216
static constexpr int ASTG = 3 * KPL;       // Kh, Kl, Vh(f16) = 27648
static constexpr int ASM  = 2 * ASTG;      // 55296
static constexpr int QLO  = 128 * KST;     // 18432

__global__ void __launch_bounds__(128, 2)
attn_mma(const __nv_bfloat16* __restrict__ Qh, const __nv_bfloat16* __restrict__ Ql,
         const __nv_bfloat16* __restrict__ Kh, const __nv_bfloat16* __restrict__ Kl,
         const __half* __restrict__ Vt, const uint32_t* __restrict__ mb,
         __nv_bfloat16* __restrict__ ctxh, __nv_bfloat16* __restrict__ ctxl)
{
    extern __shared__ __align__(128) char sm[];
    const uint32_t sb = smem_u32(sm);
    const int t = threadIdx.x, lane = t & 31, w = t >> 5;
    const int b = blockIdx.z, h = blockIdx.y, q0 = blockIdx.x * 128;
    const int g = lane >> 2, qt = lane & 3;

    {   // stage Q tile (hi/lo), extract persistent A-frags
        const char* ph = (const char*)(Qh + ((size_t)(b*S_ + q0 + t))*D_ + h*64);
        const char* pl = (const char*)(Ql + ((size_t)(b*S_ + q0 + t))*D_ + h*64);
        uint32_t d = sb + t * KST;
        #pragma unroll
        for (int i = 0; i < 8; i++) { cpa16(d + i*16, ph + i*16); cpa16(d + QLO + i*16, pl + i*16); }
        asm volatile("cp.async.commit_group;" ::: "memory");
        asm volatile("cp.async.wait_group 0;" ::: "memory");
    }
    __syncthreads();
    uint32_t qfh[2][4][4], qfl[2][4][4];
    #pragma unroll
    for (int mi = 0; mi < 2; mi++)
        #pragma unroll
        for (int kc = 0; kc < 4; kc++) {
            uint32_t a = sb + (w*32 + mi*16 + (lane & 15)) * KST + kc*32 + ((lane >> 4) << 4);
            ldsm4(qfh[mi][kc], a);
            ldsm4(qfl[mi][kc], a + QLO);
        }
    __syncthreads();

    float o[2][8][4] = {};
    float m_i[2][2], l_i[2][2];
    #pragma unroll
    for (int mi = 0; mi < 2; mi++) { m_i[mi][0]=m_i[mi][1]=-1e30f; l_i[mi][0]=l_i[mi][1]=0.f; }

    const int krow = t >> 1, khalf = (t & 1) * 64;
    #define AISSUE(c, s) do { \
        uint32_t dd = sb + (s)*ASTG + krow*KST + khalf; \
        const char* pkh = (const char*)(Kh + ((size_t)(b*S_ + (c)*64 + krow))*D_ + h*64) + khalf; \
        const char* pkl = (const char*)(Kl + ((size_t)(b*S_ + (c)*64 + krow))*D_ + h*64) + khalf; \
        const char* pvh = (const char*)(Vt + ((size_t)((b*H_+h)*64 + krow))*S_ + (c)*64) + khalf; \
        _Pragma("unroll") for (int i = 0; i < 4; i++) { \
            cpa16(dd + i*16,         pkh + i*16); \
            cpa16(dd + KPL + i*16,   pkl + i*16); \
            cpa16(dd + 2*KPL + i*16, pvh + i*16); } \
        asm volatile("cp.async.commit_group;" ::: "memory"); \
    } while (0)

    AISSUE(0, 0);
    const int NT = S_ / 64;
    for (int c = 0; c < NT; c++) {
        const int s = c & 1;
        if (c + 1 < NT) { AISSUE(c + 1, s ^ 1); asm volatile("cp.async.wait_group 1;" ::: "memory"); }
        else            { asm volatile("cp.async.wait_group 0;" ::: "memory"); }
        __syncthreads();
        const uint32_t base = sb + s * ASTG;
        const int brow = (lane & 7) + ((lane >> 4) << 3);
        const int bcsel = ((lane >> 3) & 1) << 4;

        uint2 mwa[2], mwb[2];
        #pragma unroll
        for (int mi = 0; mi < 2; mi++) {
            const uint32_t* mp = mb + (size_t)(q0 + w*32 + mi*16 + g) * (S_/32) + c*2;
            mwa[mi] = *(const uint2*)mp;
            mwb[mi] = *(const uint2*)(mp + 8 * (S_/32));
        }

        // ---- S = Q K^T (bf16, 3 terms, term-major per (kc,np) block) ----
        float sacc[2][8][4] = {};
        #pragma unroll
        for (int kc = 0; kc < 4; kc++)
            #pragma unroll
            for (int np = 0; np < 4; np++) {
                uint32_t ad = base + (np*16 + brow) * KST + kc*32 + bcsel;
                uint32_t bh[4], bl[4];
                ldsm4(bh, ad); ldsm4(bl, ad + KPL);
                // term hh (4 independent accs)
                mmabf(sacc[0][2*np],   qfh[0][kc], bh[0], bh[1]);
                mmabf(sacc[0][2*np+1], qfh[0][kc], bh[2], bh[3]);
                mmabf(sacc[1][2*np],   qfh[1][kc], bh[0], bh[1]);
                mmabf(sacc[1][2*np+1], qfh[1][kc], bh[2], bh[3]);
                // term hl
                mmabf(sacc[0][2*np],   qfh[0][kc], bl[0], bl[1]);
                mmabf(sacc[0][2*np+1], qfh[0][kc], bl[2], bl[3]);
                mmabf(sacc[1][2*np],   qfh[1][kc], bl[0], bl[1]);
                mmabf(sacc[1][2*np+1], qfh[1][kc], bl[2], bl[3]);
                // term lh
                mmabf(sacc[0][2*np],   qfl[0][kc], bh[0], bh[1]);
                mmabf(sacc[0][2*np+1], qfl[0][kc], bh[2], bh[3]);
                mmabf(sacc[1][2*np],   qfl[1][kc], bh[0], bh[1]);
                mmabf(sacc[1][2*np+1], qfl[1][kc], bh[2], bh[3]);
            }

        // ---- mask + online softmax (exp2 domain) ----
        #pragma unroll
        for (int mi = 0; mi < 2; mi++) {
            uint32_t allm = mwa[mi].x & mwa[mi].y & mwb[mi].x & mwb[mi].y;
            if (allm != 0xFFFFFFFFu) {
                #pragma unroll
                for (int nf = 0; nf < 8; nf++) {
                    uint32_t w0 = (nf < 4) ? mwa[mi].x : mwa[mi].y;
                    uint32_t w1 = (nf < 4) ? mwb[mi].x : mwb[mi].y;
                    int sh = qt*2 + (nf & 3)*8;
                    if (!((w0 >> sh) & 1))     sacc[mi][nf][0] = -1e9f;
                    if (!((w0 >> (sh+1)) & 1)) sacc[mi][nf][1] = -1e9f;
                    if (!((w1 >> sh) & 1))     sacc[mi][nf][2] = -1e9f;
                    if (!((w1 >> (sh+1)) & 1)) sacc[mi][nf][3] = -1e9f;
                }
            }
            float mx0 = -1e30f, mx1 = -1e30f;
            #pragma unroll
            for (int nf = 0; nf < 8; nf++) {
                mx0 = fmaxf(mx0, fmaxf(sacc[mi][nf][0], sacc[mi][nf][1]));
                mx1 = fmaxf(mx1, fmaxf(sacc[mi][nf][2], sacc[mi][nf][3]));
            }
            mx0 = fmaxf(mx0, __shfl_xor_sync(0xffffffffu, mx0, 1));
            mx0 = fmaxf(mx0, __shfl_xor_sync(0xffffffffu, mx0, 2));
            mx1 = fmaxf(mx1, __shfl_xor_sync(0xffffffffu, mx1, 1));
            mx1 = fmaxf(mx1, __shfl_xor_sync(0xffffffffu, mx1, 2));
            float mn0 = fmaxf(m_i[mi][0], mx0), mn1 = fmaxf(m_i[mi][1], mx1);
            float al0 = ex2(m_i[mi][0] - mn0), al1 = ex2(m_i[mi][1] - mn1);
            float s0 = 0.f, s1 = 0.f;
            #pragma unroll
            for (int nf = 0; nf < 8; nf++) {
                sacc[mi][nf][0] = ex2(sacc[mi][nf][0] - mn0);
                sacc[mi][nf][1] = ex2(sacc[mi][nf][1] - mn0);
                sacc[mi][nf][2] = ex2(sacc[mi][nf][2] - mn1);
                sacc[mi][nf][3] = ex2(sacc[mi][nf][3] - mn1);
                s0 += sacc[mi][nf][0] + sacc[mi][nf][1];
                s1 += sacc[mi][nf][2] + sacc[mi][nf][3];
            }
            s0 += __shfl_xor_sync(0xffffffffu, s0, 1);
            s0 += __shfl_xor_sync(0xffffffffu, s0, 2);
            s1 += __shfl_xor_sync(0xffffffffu, s1, 1);
            s1 += __shfl_xor_sync(0xffffffffu, s1, 2);
            l_i[mi][0] = l_i[mi][0]*al0 + s0; m_i[mi][0] = mn0;
            l_i[mi][1] = l_i[mi][1]*al1 + s1; m_i[mi][1] = mn1;
            #pragma unroll
            for (int nf = 0; nf < 8; nf++) {
                o[mi][nf][0] *= al0; o[mi][nf][1] *= al0;
                o[mi][nf][2] *= al1; o[mi][nf][3] *= al1;
            }
        }

        // ---- O += P V (fp16 single term) ----
        #pragma unroll
        for (int kc = 0; kc < 4; kc++) {
            uint32_t ph[2][4];
            #pragma unroll
            for (int mi = 0; mi < 2; mi++) {
                float* c0 = sacc[mi][2*kc];
                float* c1 = sacc[mi][2*kc+1];
                ph[mi][0] = pkh2(c0[0], c0[1]); ph[mi][1] = pkh2(c0[2], c0[3]);
                ph[mi][2] = pkh2(c1[0], c1[1]); ph[mi][3] = pkh2(c1[2], c1[3]);
            }
            #pragma unroll
            for (int np = 0; np < 4; np++) {
                uint32_t vd = base + 2*KPL + (np*16 + brow) * KST + kc*32 + bcsel;
                uint32_t vh[4];
                ldsm4(vh, vd);
                mmaf16(o[0][2*np],   ph[0], vh[0], vh[1]);
                mmaf16(o[0][2*np+1], ph[0], vh[2], vh[3]);
                mmaf16(o[1][2*np],   ph[1], vh[0], vh[1]);
                mmaf16(o[1][2*np+1], ph[1], vh[2], vh[3]);
            }
        }
        __syncthreads();
    }
    #undef AISSUE

    #pragma unroll
    for (int mi = 0; mi < 2; mi++) {
        const int r0 = q0 + w*32 + mi*16 + g;
        const float i0 = 1.f / l_i[mi][0], i1 = 1.f / l_i[mi][1];
        #pragma unroll
        for (int nf = 0; nf < 8; nf++) {
            const int col = h*64 + nf*8 + qt*2;
            float v0 = o[mi][nf][0]*i0, v1 = o[mi][nf][1]*i0;
            float v2 = o[mi][nf][2]*i1, v3 = o[mi][nf][3]*i1;
            *(uint32_t*)&ctxh[(size_t)(b*S_ + r0)*D_ + col]     = pk2(v0, v1);
            *(uint32_t*)&ctxl[(size_t)(b*S_ + r0)*D_ + col]     = pk2(bflo(v0), bflo(v1));
            *(uint32_t*)&ctxh[(size_t)(b*S_ + r0 + 8)*D_ + col] = pk2(v2, v3);
            *(uint32_t*)&ctxl[(size_t)(b*S_ + r0 + 8)*D_ + col] = pk2(bflo(v2), bflo(v3));
        }
    }
}

// ---------------------------------------------------------------------------
extern "C" void kernel_launch(void* const* d_in, const int* in_sizes, int n_in,
                              void* d_out, int out_size)
{
    const float* q  = (const float*)d_in[0];
    const float* k  = (const float*)d_in[1];
    const float* v  = (const float*)d_in[2];
    const int* mask = (const int*)  d_in[3];
    const float* Wq = (const float*)d_in[4];  const float* bq = (const float*)d_in[5];
    const float* Wk = (const float*)d_in[6];  const float* bk = (const float*)d_in[7];
    const float* Wv = (const float*)d_in[8];  const float* bv = (const float*)d_in[9];
    const float* Wo = (const float*)d_in[10]; const float* bo = (const float*)d_in[11];
    float* out = (float*)d_out;

    float *Vp;
    __nv_bfloat16 *Ahp, *Alp, *Bhp, *Blp, *Qhp, *Qlp, *Khp, *Klp;
    __half* Vtp;
    uint32_t* mbp;
    cudaGetSymbolAddress((void**)&Vp, g_V);
    cudaGetSymbolAddress((void**)&Ahp, g_Ah); cudaGetSymbolAddress((void**)&Alp, g_Al);
    cudaGetSymbolAddress((void**)&Bhp, g_Bh); cudaGetSymbolAddress((void**)&Blp, g_Bl);
    cudaGetSymbolAddress((void**)&Qhp, g_Qh); cudaGetSymbolAddress((void**)&Qlp, g_Ql);
    cudaGetSymbolAddress((void**)&Khp, g_Kh); cudaGetSymbolAddress((void**)&Klp, g_Kl);
    cudaGetSymbolAddress((void**)&Vtp, g_Vt);
    cudaGetSymbolAddress((void**)&mbp, g_mb);

    const int MA4 = NACT / 4 / 256;
    const int MW4 = (D_ * D_) / 4 / 256;
    const float QSC = 0.125f * 1.44269504088896f;

    cudaFuncSetAttribute(gemm_qkv, cudaFuncAttributeMaxDynamicSharedMemorySize, GSM);
    cudaFuncSetAttribute(gemm_o,   cudaFuncAttributeMaxDynamicSharedMemorySize, GSM);
    cudaFuncSetAttribute(attn_mma, cudaFuncAttributeMaxDynamicSharedMemorySize, ASM);

    maskbits_kernel<<<(S_*S_)/256, 256>>>(mask, mbp);
    cvt3_kernel<<<dim3(MA4, 3), 256>>>(q, k, v, Ahp, Alp, NACT / 4);
    cvt4_kernel<<<dim3(MW4, 4), 256>>>(Wq, Wk, Wv, Wo, Bhp, Blp, (D_ * D_) / 4);

    gemm_qkv<<<dim3(D_/128, (B_*S_)/128, 3), 256, GSM>>>(
        Ahp, Alp, Bhp, Blp, bq, bk, bv, Vp, Qhp, Qlp, Khp, Klp, QSC);

    cvtT_kernel<<<dim3(S_/32, D_/32, B_), 256>>>(Vp, Vtp);

    attn_mma<<<dim3(S_/128, H_, B_), 128, ASM>>>(Qhp, Qlp, Khp, Klp, Vtp, mbp, Ahp, Alp);

    gemm_o<<<dim3(D_/128, (B_*S_)/128), 256, GSM>>>(
        Ahp, Alp, Bhp + (size_t)3*D_*D_, Blp + (size_t)3*D_*D_, bo, out);
}

// round 14
// speedup vs baseline: 1.3393x; 1.3393x over previous
#include <cuda_runtime.h>
#include <cuda_bf16.h>
#include <cuda_fp16.h>
#include <cstdint>
#define B_ 2
#define S_ 2048
#define D_ 1024
#define H_ 16
#define NACT (B_*S_*D_)

__device__ float g_V[NACT];                         // fp32 V projection
__device__ __half g_Ah[3*NACT], g_Al[3*NACT];       // act hi/lo fp16 (slot0 reused for ctx)
__device__ __half g_Wh[4*D_*D_];                    // weights single fp16 plane (Wq,Wk,Wv,Wo)
__device__ __half g_Qh[NACT], g_Ql[NACT];           // attn Q planes (scaled, fp16)
__device__ __half g_Kh[NACT];                       // attn K plane (single fp16)
__device__ __half g_Vt[NACT];                       // V^T fp16 [b][h][d][s]
__device__ uint32_t g_mb[S_*S_/32];                 // mask bitplane

__device__ __forceinline__ uint32_t smem_u32(const void* p){
    uint32_t a; asm("{ .reg .u64 t; cvta.to.shared.u64 t, %1; cvt.u32.u64 %0, t; }":"=r"(a):"l"(p)); return a;
}
__device__ __forceinline__ void ldsm4(uint32_t* r, uint32_t a){
    asm volatile("ldmatrix.sync.aligned.m8n8.x4.shared.b16 {%0,%1,%2,%3}, [%4];"
        :"=r"(r[0]),"=r"(r[1]),"=r"(r[2]),"=r"(r[3]):"r"(a));
}
__device__ __forceinline__ void mmaf16(float* c, const uint32_t* a, uint32_t b0, uint32_t b1){
    asm("mma.sync.aligned.m16n8k16.row.col.f32.f16.f16.f32 "
        "{%0,%1,%2,%3}, {%4,%5,%6,%7}, {%8,%9}, {%0,%1,%2,%3};"
        :"+f"(c[0]),"+f"(c[1]),"+f"(c[2]),"+f"(c[3])
        :"r"(a[0]),"r"(a[1]),"r"(a[2]),"r"(a[3]),"r"(b0),"r"(b1));
}
__device__ __forceinline__ void cpa16(uint32_t d, const void* s){
    asm volatile("cp.async.cg.shared.global [%0], [%1], 16;"::"r"(d),"l"(s):"memory");
}
__device__ __forceinline__ uint32_t pkh2(float a, float b){
    __half2 h = __floats2half2_rn(a, b);
    return *reinterpret_cast<uint32_t*>(&h);
}
__device__ __forceinline__ float hlo(float v){      // residual after fp16 round
    return v - __half2float(__float2half_rn(v));
}
__device__ __forceinline__ float ex2(float x){
    float r; asm("ex2.approx.ftz.f32 %0, %1;":"=f"(r):"f"(x)); return r;
}

// ---------------- mask -> bitplane ----------------
__global__ void __launch_bounds__(256)
maskbits_kernel(const int* __restrict__ mask, uint32_t* __restrict__ bits)
{
    int i = blockIdx.x * 256 + threadIdx.x;
    uint32_t b = __ballot_sync(0xffffffffu, mask[i] != 0);
    if ((threadIdx.x & 31) == 0) bits[i >> 5] = b;
}

// ---------------- z-batched fp32 -> fp16 hi/lo ----------------
__global__ void __launch_bounds__(256)
cvt3_kernel(const float* __restrict__ i0, const float* __restrict__ i1,
            const float* __restrict__ i2, __half* __restrict__ hi,
            __half* __restrict__ lo, int slot_u2)
{
    int z = blockIdx.y;
    const float* in = (z == 0) ? i0 : (z == 1) ? i1 : i2;
    int i = blockIdx.x * 256 + threadIdx.x;
    float4 v = ((const float4*)in)[i];
    float a[4] = {v.x, v.y, v.z, v.w};
    unsigned short h[4], l[4];
    #pragma unroll
    for (int j = 0; j < 4; j++) {
        __half hb = __float2half_rn(a[j]);
        h[j] = __half_as_ushort(hb);
        l[j] = __half_as_ushort(__float2half_rn(a[j] - __half2float(hb)));
    }
    size_t o = (size_t)z * slot_u2 + i;
    ((uint2*)hi)[o] = make_uint2(h[0]|((uint32_t)h[1]<<16), h[2]|((uint32_t)h[3]<<16));
    ((uint2*)lo)[o] = make_uint2(l[0]|((uint32_t)l[1]<<16), l[2]|((uint32_t)l[3]<<16));
}
// weights: single fp16 plane
__global__ void __launch_bounds__(256)
cvtw_kernel(const float* __restrict__ i0, const float* __restrict__ i1,
            const float* __restrict__ i2, const float* __restrict__ i3,
            __half* __restrict__ hi, int slot_u2)
{
    int z = blockIdx.y;
    const float* in = (z == 0) ? i0 : (z == 1) ? i1 : (z == 2) ? i2 : i3;
    int i = blockIdx.x * 256 + threadIdx.x;
    float4 v = ((const float4*)in)[i];
    unsigned short h[4] = {
        __half_as_ushort(__float2half_rn(v.x)), __half_as_ushort(__float2half_rn(v.y)),
        __half_as_ushort(__float2half_rn(v.z)), __half_as_ushort(__float2half_rn(v.w))};
    ((uint2*)hi)[(size_t)z * slot_u2 + i] =
        make_uint2(h[0]|((uint32_t)h[1]<<16), h[2]|((uint32_t)h[3]<<16));
}
// V[b][s][h*64+d] -> Vt[b][h][d][s] fp16
__global__ void __launch_bounds__(256)
cvtT_kernel(const float* __restrict__ V, __half* __restrict__ oh)
{
    __shared__ float tile[32][33];
    const int s0 = blockIdx.x*32, d0 = blockIdx.y*32, b = blockIdx.z;
    const int tx = threadIdx.x & 31, ty = threadIdx.x >> 5;
    #pragma unroll
    for (int i = 0; i < 4; i++)
        tile[ty+8*i][tx] = V[((size_t)(b*S_+s0+ty+8*i))*D_ + d0+tx];
    __syncthreads();
    const int hh = d0 >> 6, dl = d0 & 63;
    #pragma unroll
    for (int i = 0; i < 4; i++) {
        int dr = ty + 8*i;
        size_t a = ((size_t)((b*H_+hh)*64 + dl + dr))*S_ + s0 + tx;
        oh[a] = __float2half(tile[tx][dr]);
    }
}

// ---------------------------------------------------------------------------
// fp16 2-term GEMM core: acc += (Ah+Al) x Wh. 3-stage cp.async ring,
// 3 planes/stage (Ah, Al, Wh), 128x128 CTA tile, BK=32.
// ---------------------------------------------------------------------------
static constexpr int PLN  = 128 * 80;    // 10240 B per plane
static constexpr int STG3 = 3 * PLN;     // 30720 per stage
static constexpr int GSM  = 3 * STG3;    // 92160

#define GISSUE(c, s) do { \
    uint32_t d = dst0 + (s) * STG3; int go = (c) * 64; \
    cpa16(d,         pAh + go); cpa16(d + 16,         pAh + go + 16); \
    cpa16(d + PLN,   pAl + go); cpa16(d + PLN + 16,   pAl + go + 16); \
    cpa16(d + 2*PLN, pW  + go); cpa16(d + 2*PLN + 16, pW  + go + 16); \
    asm volatile("cp.async.commit_group;" ::: "memory"); \
} while (0)

#define GEMM_CORE(gAh, gAl, gW, acc) do { \
    const int crow = t >> 1, coff = (t & 1) * 32; \
    const char* pAh = (const char*)((gAh) + (size_t)(bm + crow) * D_) + coff; \
    const char* pAl = (const char*)((gAl) + (size_t)(bm + crow) * D_) + coff; \
    const char* pW  = (const char*)((gW)  + (size_t)(bn + crow) * D_) + coff; \
    const uint32_t dst0 = sb + crow * 80 + coff; \
    const int NCH = D_ / 32; \
    GISSUE(0, 0); GISSUE(1, 1); \
    for (int c = 0; c < NCH; c++) { \
        const int s = c % 3; \
        if (c + 2 < NCH) { GISSUE(c + 2, (c + 2) % 3); \
            asm volatile("cp.async.wait_group 2;" ::: "memory"); } \
        else if (c + 1 < NCH) { asm volatile("cp.async.wait_group 1;" ::: "memory"); } \
        else { asm volatile("cp.async.wait_group 0;" ::: "memory"); } \
        __syncthreads(); \
        const uint32_t base = sb + s * STG3; \
        const int arow = mw + (lane & 15); \
        const int brow = nw + (lane & 7) + ((lane >> 4) << 3); \
        _Pragma("unroll") \
        for (int ks = 0; ks < 2; ks++) { \
            const int acol = ks * 32 + ((lane >> 4) << 4); \
            const int bcol = ks * 32 + (((lane >> 3) & 1) << 4); \
            uint32_t ah[2][4], al[2][4]; \
            _Pragma("unroll") \
            for (int mi = 0; mi < 2; mi++) { \
                uint32_t ad = base + (arow + mi * 16) * 80 + acol; \
                ldsm4(ah[mi], ad); ldsm4(al[mi], ad + PLN); \
            } \
            _Pragma("unroll") \
            for (int nf = 0; nf < 4; nf++) { \
                uint32_t bd = base + 2 * PLN + (brow + nf * 16) * 80 + bcol; \
                uint32_t bh[4]; \
                ldsm4(bh, bd); \
                mmaf16(acc[0][2*nf],   ah[0], bh[0], bh[1]); \
                mmaf16(acc[0][2*nf+1], ah[0], bh[2], bh[3]); \
                mmaf16(acc[1][2*nf],   ah[1], bh[0], bh[1]); \
                mmaf16(acc[1][2*nf+1], ah[1], bh[2], bh[3]); \
                mmaf16(acc[0][2*nf],   al[0], bh[0], bh[1]); \
                mmaf16(acc[0][2*nf+1], al[0], bh[2], bh[3]); \
                mmaf16(acc[1][2*nf],   al[1], bh[0], bh[1]); \
                mmaf16(acc[1][2*nf+1], al[1], bh[2], bh[3]); \
            } \
        } \
        __syncthreads(); \
    } \
} while (0)

// z-batched QKV projection: z=0 -> Q fp16 hi/lo (scaled), z=1 -> K fp16, z=2 -> V fp32
__global__ void __launch_bounds__(256, 2)
gemm_qkv(const __half* __restrict__ Ah3, const __half* __restrict__ Al3,
         const __half* __restrict__ Wh4,
         const float* __restrict__ bq, const float* __restrict__ bk,
         const float* __restrict__ bv, float* __restrict__ Vout,
         __half* __restrict__ Qh, __half* __restrict__ Ql,
         __half* __restrict__ Kh, float qsc)
{
    extern __shared__ __align__(128) char sm[];
    const uint32_t sb = smem_u32(sm);
    const int t = threadIdx.x, lane = t & 31, w = t >> 5;
    const int bm = blockIdx.y * 128, bn = blockIdx.x * 128;
    const int mw = (w >> 1) * 32, nw = (w & 1) * 64;
    const int z = blockIdx.z;
    const __half* Ah = Ah3 + (size_t)z * NACT;
    const __half* Al = Al3 + (size_t)z * NACT;
    const __half* W  = Wh4 + (size_t)z * D_ * D_;
    const float* bias = (z == 0) ? bq : (z == 1) ? bk : bv;

    float acc[2][8][4] = {};
    GEMM_CORE(Ah, Al, W, acc);

    const float osc = (z == 0) ? qsc : 1.0f;
    #pragma unroll
    for (int mi = 0; mi < 2; mi++) {
        const int r0 = bm + mw + mi * 16 + (lane >> 2);
        #pragma unroll
        for (int nj = 0; nj < 8; nj++) {
            const int col = bn + nw + nj * 8 + (lane & 3) * 2;
            float2 bv2 = *(const float2*)&bias[col];
            float* c = acc[mi][nj];
            float v0 = (c[0] + bv2.x) * osc, v1 = (c[1] + bv2.y) * osc;
            float v2 = (c[2] + bv2.x) * osc, v3 = (c[3] + bv2.y) * osc;
            if (z == 2) {
                *(float2*)&Vout[(size_t)r0 * D_ + col] = make_float2(v0, v1);
                *(float2*)&Vout[(size_t)(r0 + 8) * D_ + col] = make_float2(v2, v3);
            } else if (z == 1) {
                *(uint32_t*)&Kh[(size_t)r0 * D_ + col]       = pkh2(v0, v1);
                *(uint32_t*)&Kh[(size_t)(r0 + 8) * D_ + col] = pkh2(v2, v3);
            } else {
                *(uint32_t*)&Qh[(size_t)r0 * D_ + col]       = pkh2(v0, v1);
                *(uint32_t*)&Ql[(size_t)r0 * D_ + col]       = pkh2(hlo(v0), hlo(v1));
                *(uint32_t*)&Qh[(size_t)(r0 + 8) * D_ + col] = pkh2(v2, v3);
                *(uint32_t*)&Ql[(size_t)(r0 + 8) * D_ + col] = pkh2(hlo(v2), hlo(v3));
            }
        }
    }
}

// O projection: fp32 out
__global__ void __launch_bounds__(256, 2)
gemm_o(const __half* __restrict__ Ah, const __half* __restrict__ Al,
       const __half* __restrict__ W, const float* __restrict__ bias,
       float* __restrict__ outf)
{
    extern __shared__ __align__(128) char sm[];
    const uint32_t sb = smem_u32(sm);
    const int t = threadIdx.x, lane = t & 31, w = t >> 5;
    const int bm = blockIdx.y * 128, bn = blockIdx.x * 128;
    const int mw = (w >> 1) * 32, nw = (w & 1) * 64;

    float acc[2][8][4] = {};
    GEMM_CORE(Ah, Al, W, acc);

    #pragma unroll
    for (int mi = 0; mi < 2; mi++) {
        const int r0 = bm + mw + mi * 16 + (lane >> 2);
        #pragma unroll
        for (int nj = 0; nj < 8; nj++) {
            const int col = bn + nw + nj * 8 + (lane & 3) * 2;
            float2 bv2 = *(const float2*)&bias[col];
            float* c = acc[mi][nj];
            *(float2*)&outf[(size_t)r0 * D_ + col] = make_float2(c[0] + bv2.x, c[1] + bv2.y);
            *(float2*)&outf[(size_t)(r0 + 8) * D_ + col] = make_float2(c[2] + bv2.x, c[3] + bv2.y);
        }
    }
}

// ---------------------------------------------------------------------------
// fp16 flash attention: QK^T = (Qh+Ql) x Kh (2 terms), PV fp16x1,
// exp2 softmax, bitmask masking, 3-stage K/V ring, fp16 hi/lo ctx output.
// ---------------------------------------------------------------------------
static constexpr int KST   = 144;
static constexpr int KPL   = 64 * KST;     // 9216
static constexpr int ASTG2 = 2 * KPL;      // Kh + V = 18432
static constexpr int ASM   = 3 * ASTG2;    // 55296
static constexpr int QLO   = 128 * KST;    // 18432 (Q lo plane offset in prologue)

__global__ void __launch_bounds__(128, 2)
attn_mma(const __half* __restrict__ Qh, const __half* __restrict__ Ql,
         const __half* __restrict__ Kh, const __half* __restrict__ Vt,
         const uint32_t* __restrict__ mb,
         __half* __restrict__ ctxh, __half* __restrict__ ctxl)
{
    extern __shared__ __align__(128) char sm[];
    const uint32_t sb = smem_u32(sm);
    const int t = threadIdx.x, lane = t & 31, w = t >> 5;
    const int b = blockIdx.z, h = blockIdx.y, q0 = blockIdx.x * 128;
    const int g = lane >> 2, qt = lane & 3;

    {   // stage Q tile (hi/lo), extract persistent A-frags
        const char* ph = (const char*)(Qh + ((size_t)(b*S_ + q0 + t))*D_ + h*64);
        const char* pl = (const char*)(Ql + ((size_t)(b*S_ + q0 + t))*D_ + h*64);
        uint32_t d = sb + t * KST;
        #pragma unroll
        for (int i = 0; i < 8; i++) { cpa16(d + i*16, ph + i*16); cpa16(d + QLO + i*16, pl + i*16); }
        asm volatile("cp.async.commit_group;" ::: "memory");
        asm volatile("cp.async.wait_group 0;" ::: "memory");
    }
    __syncthreads();
    uint32_t qfh[2][4][4], qfl[2][4][4];
    #pragma unroll
    for (int mi = 0; mi < 2; mi++)
        #pragma unroll
        for (int kc = 0; kc < 4; kc++) {
            uint32_t a = sb + (w*32 + mi*16 + (lane & 15)) * KST + kc*32 + ((lane >> 4) << 4);
            ldsm4(qfh[mi][kc], a);
            ldsm4(qfl[mi][kc], a + QLO);
        }
    __syncthreads();

    float o[2][8][4] = {};
    float m_i[2][2], l_i[2][2];
    #pragma unroll
    for (int mi = 0; mi < 2; mi++) { m_i[mi][0]=m_i[mi][1]=-1e30f; l_i[mi][0]=l_i[mi][1]=0.f; }

    const int krow = t >> 1, khalf = (t & 1) * 64;
    #define AISSUE(c, s) do { \
        uint32_t dd = sb + (s)*ASTG2 + krow*KST + khalf; \
        const char* pkh = (const char*)(Kh + ((size_t)(b*S_ + (c)*64 + krow))*D_ + h*64) + khalf; \
        const char* pvh = (const char*)(Vt + ((size_t)((b*H_+h)*64 + krow))*S_ + (c)*64) + khalf; \
        _Pragma("unroll") for (int i = 0; i < 4; i++) { \
            cpa16(dd + i*16,       pkh + i*16); \
            cpa16(dd + KPL + i*16, pvh + i*16); } \
        asm volatile("cp.async.commit_group;" ::: "memory"); \
    } while (0)

    const int NT = S_ / 64;
    AISSUE(0, 0); AISSUE(1, 1);
    for (int c = 0; c < NT; c++) {
        const int s = c % 3;
        if (c + 2 < NT) { AISSUE(c + 2, (c + 2) % 3);
            asm volatile("cp.async.wait_group 2;" ::: "memory"); }
        else if (c + 1 < NT) { asm volatile("cp.async.wait_group 1;" ::: "memory"); }
        else { asm volatile("cp.async.wait_group 0;" ::: "memory"); }
        __syncthreads();
        const uint32_t base = sb + s * ASTG2;
        const int brow = (lane & 7) + ((lane >> 4) << 3);
        const int bcsel = ((lane >> 3) & 1) << 4;

        uint2 mwa[2], mwb[2];
        #pragma unroll
        for (int mi = 0; mi < 2; mi++) {
            const uint32_t* mp = mb + (size_t)(q0 + w*32 + mi*16 + g) * (S_/32) + c*2;
            mwa[mi] = *(const uint2*)mp;
            mwb[mi] = *(const uint2*)(mp + 8 * (S_/32));
        }

        // ---- S = Q K^T (fp16, 2 terms) ----
        float sacc[2][8][4] = {};
        #pragma unroll
        for (int kc = 0; kc < 4; kc++)
            #pragma unroll
            for (int np = 0; np < 4; np++) {
                uint32_t ad = base + (np*16 + brow) * KST + kc*32 + bcsel;
                uint32_t kf[4];
                ldsm4(kf, ad);
                mmaf16(sacc[0][2*np],   qfh[0][kc], kf[0], kf[1]);
                mmaf16(sacc[0][2*np+1], qfh[0][kc], kf[2], kf[3]);
                mmaf16(sacc[1][2*np],   qfh[1][kc], kf[0], kf[1]);
                mmaf16(sacc[1][2*np+1], qfh[1][kc], kf[2], kf[3]);
                mmaf16(sacc[0][2*np],   qfl[0][kc], kf[0], kf[1]);
                mmaf16(sacc[0][2*np+1], qfl[0][kc], kf[2], kf[3]);
                mmaf16(sacc[1][2*np],   qfl[1][kc], kf[0], kf[1]);
                mmaf16(sacc[1][2*np+1], qfl[1][kc], kf[2], kf[3]);
            }

        // ---- mask + online softmax (exp2 domain) ----
        #pragma unroll
        for (int mi = 0; mi < 2; mi++) {
            uint32_t allm = mwa[mi].x & mwa[mi].y & mwb[mi].x & mwb[mi].y;
            if (allm != 0xFFFFFFFFu) {
                #pragma unroll
                for (int nf = 0; nf < 8; nf++) {
                    uint32_t w0 = (nf < 4) ? mwa[mi].x : mwa[mi].y;
                    uint32_t w1 = (nf < 4) ? mwb[mi].x : mwb[mi].y;
                    int sh = qt*2 + (nf & 3)*8;
                    if (!((w0 >> sh) & 1))     sacc[mi][nf][0] = -1e9f;
                    if (!((w0 >> (sh+1)) & 1)) sacc[mi][nf][1] = -1e9f;
                    if (!((w1 >> sh) & 1))     sacc[mi][nf][2] = -1e9f;
                    if (!((w1 >> (sh+1)) & 1)) sacc[mi][nf][3] = -1e9f;
                }
            }
            float mx0 = -1e30f, mx1 = -1e30f;
            #pragma unroll
            for (int nf = 0; nf < 8; nf++) {
                mx0 = fmaxf(mx0, fmaxf(sacc[mi][nf][0], sacc[mi][nf][1]));
                mx1 = fmaxf(mx1, fmaxf(sacc[mi][nf][2], sacc[mi][nf][3]));
            }
            mx0 = fmaxf(mx0, __shfl_xor_sync(0xffffffffu, mx0, 1));
            mx0 = fmaxf(mx0, __shfl_xor_sync(0xffffffffu, mx0, 2));
            mx1 = fmaxf(mx1, __shfl_xor_sync(0xffffffffu, mx1, 1));
            mx1 = fmaxf(mx1, __shfl_xor_sync(0xffffffffu, mx1, 2));
            float mn0 = fmaxf(m_i[mi][0], mx0), mn1 = fmaxf(m_i[mi][1], mx1);
            float al0 = ex2(m_i[mi][0] - mn0), al1 = ex2(m_i[mi][1] - mn1);
            float s0 = 0.f, s1 = 0.f;
            #pragma unroll
            for (int nf = 0; nf < 8; nf++) {
                sacc[mi][nf][0] = ex2(sacc[mi][nf][0] - mn0);
                sacc[mi][nf][1] = ex2(sacc[mi][nf][1] - mn0);
                sacc[mi][nf][2] = ex2(sacc[mi][nf][2] - mn1);
                sacc[mi][nf][3] = ex2(sacc[mi][nf][3] - mn1);
                s0 += sacc[mi][nf][0] + sacc[mi][nf][1];
                s1 += sacc[mi][nf][2] + sacc[mi][nf][3];
            }
            s0 += __shfl_xor_sync(0xffffffffu, s0, 1);
            s0 += __shfl_xor_sync(0xffffffffu, s0, 2);
            s1 += __shfl_xor_sync(0xffffffffu, s1, 1);
            s1 += __shfl_xor_sync(0xffffffffu, s1, 2);
            l_i[mi][0] = l_i[mi][0]*al0 + s0; m_i[mi][0] = mn0;
            l_i[mi][1] = l_i[mi][1]*al1 + s1; m_i[mi][1] = mn1;
            #pragma unroll
            for (int nf = 0; nf < 8; nf++) {
                o[mi][nf][0] *= al0; o[mi][nf][1] *= al0;
                o[mi][nf][2] *= al1; o[mi][nf][3] *= al1;
            }
        }

        // ---- O += P V (fp16 single term) ----
        #pragma unroll
        for (int kc = 0; kc < 4; kc++) {
            uint32_t ph[2][4];
            #pragma unroll
            for (int mi = 0; mi < 2; mi++) {
                float* c0 = sacc[mi][2*kc];
                float* c1 = sacc[mi][2*kc+1];
                ph[mi][0] = pkh2(c0[0], c0[1]); ph[mi][1] = pkh2(c0[2], c0[3]);
                ph[mi][2] = pkh2(c1[0], c1[1]); ph[mi][3] = pkh2(c1[2], c1[3]);
            }
            #pragma unroll
            for (int np = 0; np < 4; np++) {
                uint32_t vd = base + KPL + (np*16 + brow) * KST + kc*32 + bcsel;
                uint32_t vh[4];
                ldsm4(vh, vd);
                mmaf16(o[0][2*np],   ph[0], vh[0], vh[1]);
                mmaf16(o[0][2*np+1], ph[0], vh[2], vh[3]);
                mmaf16(o[1][2*np],   ph[1], vh[0], vh[1]);
                mmaf16(o[1][2*np+1], ph[1], vh[2], vh[3]);
            }
        }
        __syncthreads();
    }
    #undef AISSUE

    #pragma unroll
    for (int mi = 0; mi < 2; mi++) {
        const int r0 = q0 + w*32 + mi*16 + g;
        const float i0 = 1.f / l_i[mi][0], i1 = 1.f / l_i[mi][1];
        #pragma unroll
        for (int nf = 0; nf < 8; nf++) {
            const int col = h*64 + nf*8 + qt*2;
            float v0 = o[mi][nf][0]*i0, v1 = o[mi][nf][1]*i0;
            float v2 = o[mi][nf][2]*i1, v3 = o[mi][nf][3]*i1;
            *(uint32_t*)&ctxh[(size_t)(b*S_ + r0)*D_ + col]     = pkh2(v0, v1);
            *(uint32_t*)&ctxl[(size_t)(b*S_ + r0)*D_ + col]     = pkh2(hlo(v0), hlo(v1));
            *(uint32_t*)&ctxh[(size_t)(b*S_ + r0 + 8)*D_ + col] = pkh2(v2, v3);
            *(uint32_t*)&ctxl[(size_t)(b*S_ + r0 + 8)*D_ + col] = pkh2(hlo(v2), hlo(v3));
        }
    }
}

// ---------------------------------------------------------------------------
extern "C" void kernel_launch(void* const* d_in, const int* in_sizes, int n_in,
                              void* d_out, int out_size)
{
    const float* q  = (const float*)d_in[0];
    const float* k  = (const float*)d_in[1];
    const float* v  = (const float*)d_in[2];
    const int* mask = (const int*)  d_in[3];
    const float* Wq = (const float*)d_in[4];  const float* bq = (const float*)d_in[5];
    const float* Wk = (const float*)d_in[6];  const float* bk = (const float*)d_in[7];
    const float* Wv = (const float*)d_in[8];  const float* bv = (const float*)d_in[9];
    const float* Wo = (const float*)d_in[10]; const float* bo = (const float*)d_in[11];
    float* out = (float*)d_out;

    float *Vp;
    __half *Ahp, *Alp, *Whp, *Qhp, *Qlp, *Khp, *Vtp;
    uint32_t* mbp;
    cudaGetSymbolAddress((void**)&Vp, g_V);
    cudaGetSymbolAddress((void**)&Ahp, g_Ah); cudaGetSymbolAddress((void**)&Alp, g_Al);
    cudaGetSymbolAddress((void**)&Whp, g_Wh);
    cudaGetSymbolAddress((void**)&Qhp, g_Qh); cudaGetSymbolAddress((void**)&Qlp, g_Ql);
    cudaGetSymbolAddress((void**)&Khp, g_Kh);
    cudaGetSymbolAddress((void**)&Vtp, g_Vt);
    cudaGetSymbolAddress((void**)&mbp, g_mb);

    const int MA4 = NACT / 4 / 256;
    const int MW4 = (D_ * D_) / 4 / 256;
    const float QSC = 0.125f * 1.44269504088896f;

    cudaFuncSetAttribute(gemm_qkv, cudaFuncAttributeMaxDynamicSharedMemorySize, GSM);
    cudaFuncSetAttribute(gemm_o,   cudaFuncAttributeMaxDynamicSharedMemorySize, GSM);
    cudaFuncSetAttribute(attn_mma, cudaFuncAttributeMaxDynamicSharedMemorySize, ASM);

    maskbits_kernel<<<(S_*S_)/256, 256>>>(mask, mbp);
    cvt3_kernel<<<dim3(MA4, 3), 256>>>(q, k, v, Ahp, Alp, NACT / 4);
    cvtw_kernel<<<dim3(MW4, 4), 256>>>(Wq, Wk, Wv, Wo, Whp, (D_ * D_) / 4);

    gemm_qkv<<<dim3(D_/128, (B_*S_)/128, 3), 256, GSM>>>(
        Ahp, Alp, Whp, bq, bk, bv, Vp, Qhp, Qlp, Khp, QSC);

    cvtT_kernel<<<dim3(S_/32, D_/32, B_), 256>>>(Vp, Vtp);

    attn_mma<<<dim3(S_/128, H_, B_), 128, ASM>>>(Qhp, Qlp, Khp, Vtp, mbp, Ahp, Alp);

    gemm_o<<<dim3(D_/128, (B_*S_)/128), 256, GSM>>>(
        Ahp, Alp, Whp + (size_t)3*D_*D_, bo, out);
}